// round 5
// baseline (speedup 1.0000x reference)
#include <cuda_runtime.h>
#include <cstdint>
#include <math.h>

#define BB 4096
#define EE 1024
#define HH 1024
#define CC 1024
#define DD 3072

// ---- scratch (device globals; allocation-rule-safe) ----
__device__ float g_preact[(size_t)BB * 4 * HH];  // [B,4H] fp32 gate preacts
__device__ float g_Acat  [(size_t)BB * DD];      // [B,3072] tf32 concat(emb,hid,ctx)
__device__ float g_Wgcat [(size_t)4 * HH * DD];  // [4096,3072] tf32 gate weights (i,f,o,g)
__device__ float g_A1cat [(size_t)BB * 2048];    // [B,2048] tf32 (hidden|ctx)
__device__ float g_Whc   [(size_t)EE * 2048];    // [1024,2048] tf32 (Wh|Wc)
__device__ float g_Wpt   [(size_t)EE * EE];      // [1024,1024] tf32 Wp
__device__ float g_residT[(size_t)BB * EE];      // [B,1024] tf32 resid
__device__ float g_bias0 [4 * HH];               // gate bias concat
__device__ float g_bias1 [EE];                   // bh+bc

__device__ __forceinline__ float f2tf(float x) {
    uint32_t r; asm("cvt.rna.tf32.f32 %0, %1;" : "=r"(r) : "f"(x));
    return __uint_as_float(r);
}
__device__ __forceinline__ void mma_tf32(float* c, const uint32_t* a, const uint32_t* b) {
    asm volatile(
        "mma.sync.aligned.m16n8k8.row.col.f32.tf32.tf32.f32 "
        "{%0,%1,%2,%3}, {%4,%5,%6,%7}, {%8,%9}, {%0,%1,%2,%3};"
        : "+f"(c[0]), "+f"(c[1]), "+f"(c[2]), "+f"(c[3])
        : "r"(a[0]), "r"(a[1]), "r"(a[2]), "r"(a[3]), "r"(b[0]), "r"(b[1]));
}

// ---------------------------------------------------------------------------
// Precompute: tf32-convert a [rows x 1024-or-srcld] block into a strided dest.
// ---------------------------------------------------------------------------
__global__ void cvt_seg(const float* __restrict__ src, float* __restrict__ dst,
                        int srcld4, int dstld, int dstoff, int total4)
{
    const int i = blockIdx.x * blockDim.x + threadIdx.x;
    if (i >= total4) return;
    const int row = i / srcld4;
    const int c4  = i - row * srcld4;
    const float4 v = reinterpret_cast<const float4*>(src)[(size_t)row * srcld4 + c4];
    float4 o = make_float4(f2tf(v.x), f2tf(v.y), f2tf(v.z), f2tf(v.w));
    *reinterpret_cast<float4*>(dst + (size_t)row * dstld + dstoff + c4 * 4) = o;
}

__global__ void bias_prep(const float* __restrict__ bi, const float* __restrict__ bf,
                          const float* __restrict__ bo, const float* __restrict__ bg,
                          const float* __restrict__ bh, const float* __restrict__ bc)
{
    const int i = blockIdx.x * blockDim.x + threadIdx.x;
    if (i < 4096) {
        const int g = i >> 10, n = i & 1023;
        g_bias0[i] = (g == 0) ? bi[n] : (g == 1) ? bf[n] : (g == 2) ? bo[n] : bg[n];
    }
    if (i < 1024) g_bias1[i] = bh[i] + bc[i];
}

// ---------------------------------------------------------------------------
// Smem-free tf32 MMA GEMM. CTA tile 128(M) x 256(N), 512 threads, 16 warps
// in 4x4; warp tile 32x64 (mi=2 m16-tiles, nj=8 n8-tiles). All operands are
// pre-converted tf32 bits in row-major [rows x KD] with matching fragment
// k-slot mapping: slot t <- data k+2t, slot t+4 <- data k+2t+1 (LDG.64 dense).
// Intra-CTA reuse via L1; no shared memory, no barriers.
// MODE 0: out fp32 = acc + bias            (preact, ldo=4096)
// MODE 1: out tf32 = cvt(acc + bias + addend)  (resid, ldo=1024)
// MODE 2: out fp32 = acc + bias            (prediction, ldo=1024)
// ---------------------------------------------------------------------------
template<int MODE, int KD>
__global__ __launch_bounds__(512)
void mma_gemm(const float* __restrict__ A, const float* __restrict__ W,
              const float* __restrict__ bias, const float* __restrict__ addend,
              float* __restrict__ out, int ldo)
{
    const int tid  = threadIdx.x;
    const int w    = tid >> 5, lane = tid & 31;
    const int wm   = w >> 2,  wn = w & 3;
    const int m0   = blockIdx.y * 128 + wm * 32;
    const int n0   = blockIdx.x * 256 + wn * 64;
    const int grp  = lane >> 2, tig = lane & 3;

    float acc[2][8][4];
#pragma unroll
    for (int i = 0; i < 2; i++)
#pragma unroll
        for (int j = 0; j < 8; j++)
#pragma unroll
            for (int v = 0; v < 4; v++) acc[i][j][v] = 0.0f;

    const float* aP = A + (size_t)(m0 + grp) * KD + 2 * tig;
    const float* bP = W + (size_t)(n0 + grp) * KD + 2 * tig;

#pragma unroll 4
    for (int k8 = 0; k8 < KD / 8; k8++) {
        const float2 a00 = *reinterpret_cast<const float2*>(aP);             // row grp,   mi=0
        const float2 a01 = *reinterpret_cast<const float2*>(aP + 8  * KD);   // row grp+8, mi=0
        const float2 a10 = *reinterpret_cast<const float2*>(aP + 16 * KD);   // mi=1
        const float2 a11 = *reinterpret_cast<const float2*>(aP + 24 * KD);
        float2 bfr[8];
#pragma unroll
        for (int nj = 0; nj < 8; nj++)
            bfr[nj] = *reinterpret_cast<const float2*>(bP + nj * 8 * KD);

        uint32_t af0[4] = { __float_as_uint(a00.x), __float_as_uint(a01.x),
                            __float_as_uint(a00.y), __float_as_uint(a01.y) };
        uint32_t af1[4] = { __float_as_uint(a10.x), __float_as_uint(a11.x),
                            __float_as_uint(a10.y), __float_as_uint(a11.y) };
#pragma unroll
        for (int nj = 0; nj < 8; nj++) {
            uint32_t bb[2] = { __float_as_uint(bfr[nj].x), __float_as_uint(bfr[nj].y) };
            mma_tf32(acc[0][nj], af0, bb);
            mma_tf32(acc[1][nj], af1, bb);
        }
        aP += 8; bP += 8;
    }

    // ---- epilogue ----
    const int gr = lane >> 2;
    const int gc = (lane & 3) * 2;
#pragma unroll
    for (int mi = 0; mi < 2; mi++) {
        const int gm = m0 + mi * 16 + gr;
#pragma unroll
        for (int nj = 0; nj < 8; nj++) {
            const int gn = n0 + nj * 8 + gc;
            const float bv0 = bias[gn], bv1 = bias[gn + 1];
            float2 r0 = make_float2(acc[mi][nj][0] + bv0, acc[mi][nj][1] + bv1);
            float2 r1 = make_float2(acc[mi][nj][2] + bv0, acc[mi][nj][3] + bv1);
            if (MODE == 1) {
                const float2 d0 = *reinterpret_cast<const float2*>(
                    addend + (size_t)gm * 1024 + gn);
                const float2 d1 = *reinterpret_cast<const float2*>(
                    addend + (size_t)(gm + 8) * 1024 + gn);
                r0 = make_float2(f2tf(r0.x + d0.x), f2tf(r0.y + d0.y));
                r1 = make_float2(f2tf(r1.x + d1.x), f2tf(r1.y + d1.y));
            }
            *reinterpret_cast<float2*>(out + (size_t)gm * ldo + gn)       = r0;
            *reinterpret_cast<float2*>(out + (size_t)(gm + 8) * ldo + gn) = r1;
        }
    }
}

// ---------------------------------------------------------------------------
// Elementwise LSTM cell; also emits tf32 hidden into A1cat[:, 0:1024].
// ---------------------------------------------------------------------------
__device__ __forceinline__ float sigf(float x) { return 1.0f / (1.0f + __expf(-x)); }
__device__ __forceinline__ float tanhfast(float x) { return 2.0f * sigf(2.0f * x) - 1.0f; }

__global__ void lstm_elem(const float4* __restrict__ pre,
                          const float4* __restrict__ cprev,
                          float4* __restrict__ hidden,
                          float4* __restrict__ cell)
{
    const int idx = blockIdx.x * blockDim.x + threadIdx.x;  // BB*HH/4
    const int b  = idx >> 8;
    const int h4 = idx & 255;
    const size_t base = (size_t)b * 1024;
    const float4 pi = pre[base + h4];
    const float4 pf = pre[base + 256 + h4];
    const float4 po = pre[base + 512 + h4];
    const float4 pg = pre[base + 768 + h4];
    const float4 cp = cprev[idx];

    const float c0 = sigf(pf.x) * cp.x + sigf(pi.x) * tanhfast(pg.x);
    const float c1 = sigf(pf.y) * cp.y + sigf(pi.y) * tanhfast(pg.y);
    const float c2 = sigf(pf.z) * cp.z + sigf(pi.z) * tanhfast(pg.z);
    const float c3 = sigf(pf.w) * cp.w + sigf(pi.w) * tanhfast(pg.w);

    const float h0 = sigf(po.x) * tanhfast(c0);
    const float h1 = sigf(po.y) * tanhfast(c1);
    const float h2 = sigf(po.z) * tanhfast(c2);
    const float h3 = sigf(po.w) * tanhfast(c3);

    cell[idx]   = make_float4(c0, c1, c2, c3);
    hidden[idx] = make_float4(h0, h1, h2, h3);

    // tf32 hidden -> A1cat cols [0,1024)
    float4* a1 = reinterpret_cast<float4*>(g_A1cat + (size_t)b * 2048 + h4 * 4);
    *a1 = make_float4(f2tf(h0), f2tf(h1), f2tf(h2), f2tf(h3));
}

// ---------------------------------------------------------------------------
extern "C" void kernel_launch(void* const* d_in, const int* in_sizes, int n_in,
                              void* d_out, int out_size)
{
    (void)in_sizes; (void)n_in; (void)out_size;

    const float* emb = (const float*)d_in[0];
    const float* hid = (const float*)d_in[1];
    const float* cpr = (const float*)d_in[2];
    const float* ctx = (const float*)d_in[3];
    const float* Wi  = (const float*)d_in[4];  const float* bi = (const float*)d_in[5];
    const float* Wf  = (const float*)d_in[6];  const float* bf = (const float*)d_in[7];
    const float* Wo  = (const float*)d_in[8];  const float* bo = (const float*)d_in[9];
    const float* Wg  = (const float*)d_in[10]; const float* bg = (const float*)d_in[11];
    const float* Wc  = (const float*)d_in[12]; const float* bc = (const float*)d_in[13];
    const float* Wh  = (const float*)d_in[14]; const float* bh = (const float*)d_in[15];
    const float* Wp  = (const float*)d_in[16]; const float* bp = (const float*)d_in[17];

    float* out     = (float*)d_out;
    float* pred    = out;
    float* hiddenO = out + (size_t)BB * EE;
    float* cellO   = hiddenO + (size_t)BB * HH;

    float *preP, *AcatP, *WgP, *A1P, *WhcP, *WpP, *residP, *b0P, *b1P;
    cudaGetSymbolAddress((void**)&preP,   g_preact);
    cudaGetSymbolAddress((void**)&AcatP,  g_Acat);
    cudaGetSymbolAddress((void**)&WgP,    g_Wgcat);
    cudaGetSymbolAddress((void**)&A1P,    g_A1cat);
    cudaGetSymbolAddress((void**)&WhcP,   g_Whc);
    cudaGetSymbolAddress((void**)&WpP,    g_Wpt);
    cudaGetSymbolAddress((void**)&residP, g_residT);
    cudaGetSymbolAddress((void**)&b0P,    g_bias0);
    cudaGetSymbolAddress((void**)&b1P,    g_bias1);

    const int T = 256;
    // ---- precompute: tf32 conversions + concats ----
    {   // A_cat = [emb | hid | ctx], dstld 3072
        const int n4 = BB * 256;
        cvt_seg<<<(n4 + T - 1) / T, T>>>(emb, AcatP, 256, DD, 0,    n4);
        cvt_seg<<<(n4 + T - 1) / T, T>>>(hid, AcatP, 256, DD, 1024, n4);
        cvt_seg<<<(n4 + T - 1) / T, T>>>(ctx, AcatP, 256, DD, 2048, n4);
        // ctx -> A1cat cols [1024,2048)
        cvt_seg<<<(n4 + T - 1) / T, T>>>(ctx, A1P, 256, 2048, 1024, n4);
    }
    {   // gate weights (contiguous copies)
        const int n4 = HH * (DD / 4);
        cvt_seg<<<(n4 + T - 1) / T, T>>>(Wi, WgP,                       DD / 4, DD, 0, n4);
        cvt_seg<<<(n4 + T - 1) / T, T>>>(Wf, WgP + (size_t)1 * HH * DD, DD / 4, DD, 0, n4);
        cvt_seg<<<(n4 + T - 1) / T, T>>>(Wo, WgP + (size_t)2 * HH * DD, DD / 4, DD, 0, n4);
        cvt_seg<<<(n4 + T - 1) / T, T>>>(Wg, WgP + (size_t)3 * HH * DD, DD / 4, DD, 0, n4);
    }
    {   // Whc = [Wh | Wc] along K
        const int n4 = EE * 256;
        cvt_seg<<<(n4 + T - 1) / T, T>>>(Wh, WhcP, 256, 2048, 0,    n4);
        cvt_seg<<<(n4 + T - 1) / T, T>>>(Wc, WhcP, 256, 2048, 1024, n4);
        cvt_seg<<<(n4 + T - 1) / T, T>>>(Wp, WpP,  256, 1024, 0,    n4);
    }
    bias_prep<<<16, 256>>>(bi, bf, bo, bg, bh, bc);

    // ---- 1) gates: [B,4H] preact ----
    mma_gemm<0, DD><<<dim3(16, 32), 512>>>(AcatP, WgP, b0P, nullptr, preP, 4 * HH);

    // ---- 2) cell update (also writes tf32 hidden into A1cat) ----
    lstm_elem<<<4096, 256>>>((const float4*)preP, (const float4*)cpr,
                             (float4*)hiddenO, (float4*)cellO);

    // ---- 3) resid (tf32) = cvt(emb + hidden@Wh^T + ctx@Wc^T + bh + bc) ----
    mma_gemm<1, 2048><<<dim3(4, 32), 512>>>(A1P, WhcP, b1P, emb, residP, EE);

    // ---- 4) prediction = resid @ Wp^T + bp ----
    mma_gemm<2, 1024><<<dim3(4, 32), 512>>>(residP, WpP, bp, nullptr, pred, EE);
}

// round 9
// speedup vs baseline: 1.8039x; 1.8039x over previous
#include <cuda_runtime.h>
#include <cstdint>
#include <math.h>

#define BB 4096
#define EE 1024
#define HH 1024
#define CC 1024
#define DD 3072

// ---- scratch (device globals; allocation-rule-safe) ----
__device__ float g_preact[(size_t)BB * 4 * HH];  // [B,4H] fp32 gate preacts
__device__ float g_Acat  [(size_t)BB * DD];      // [B,3072] tf32 concat(emb,hid,ctx)
__device__ float g_Wgcat [(size_t)4 * HH * DD];  // [4096,3072] tf32 gate weights
__device__ float g_A1cat [(size_t)BB * 2048];    // [B,2048] tf32 (hidden|ctx)
__device__ float g_Whc   [(size_t)EE * 2048];    // [1024,2048] tf32 (Wh|Wc)
__device__ float g_Wpt   [(size_t)EE * EE];      // [1024,1024] tf32 Wp
__device__ float g_residT[(size_t)BB * EE];      // [B,1024] tf32 resid
__device__ float g_bias0 [4 * HH];
__device__ float g_bias1 [EE];

__device__ __forceinline__ float f2tf(float x) {
    uint32_t r; asm("cvt.rna.tf32.f32 %0, %1;" : "=r"(r) : "f"(x));
    return __uint_as_float(r);
}
__device__ __forceinline__ uint32_t smem_u32(const void* p) {
    uint32_t a;
    asm("{ .reg .u64 t; cvta.to.shared.u64 t, %1; cvt.u32.u64 %0, t; }" : "=r"(a) : "l"(p));
    return a;
}
__device__ __forceinline__ void mma_tf32(float* c, const uint32_t* a, const uint32_t* b) {
    asm volatile(
        "mma.sync.aligned.m16n8k8.row.col.f32.tf32.tf32.f32 "
        "{%0,%1,%2,%3}, {%4,%5,%6,%7}, {%8,%9}, {%0,%1,%2,%3};"
        : "+f"(c[0]), "+f"(c[1]), "+f"(c[2]), "+f"(c[3])
        : "r"(a[0]), "r"(a[1]), "r"(a[2]), "r"(a[3]), "r"(b[0]), "r"(b[1]));
}
__device__ __forceinline__ void cp16(uint32_t d, const float* g) {
    asm volatile("cp.async.cg.shared.global [%0], [%1], 16;" :: "r"(d), "l"(g));
}

// ---------------------------------------------------------------------------
// Precompute: tf32-convert (RNA) a row-major block into a strided dest.
// ---------------------------------------------------------------------------
__global__ void cvt_seg(const float* __restrict__ src, float* __restrict__ dst,
                        int srcld4, int dstld, int dstoff, int total4)
{
    const int i = blockIdx.x * blockDim.x + threadIdx.x;
    if (i >= total4) return;
    const int row = i / srcld4;
    const int c4  = i - row * srcld4;
    const float4 v = reinterpret_cast<const float4*>(src)[(size_t)row * srcld4 + c4];
    float4 o = make_float4(f2tf(v.x), f2tf(v.y), f2tf(v.z), f2tf(v.w));
    *reinterpret_cast<float4*>(dst + (size_t)row * dstld + dstoff + c4 * 4) = o;
}

__global__ void bias_prep(const float* __restrict__ bi, const float* __restrict__ bf,
                          const float* __restrict__ bo, const float* __restrict__ bg,
                          const float* __restrict__ bh, const float* __restrict__ bc)
{
    const int i = blockIdx.x * blockDim.x + threadIdx.x;
    if (i < 4096) {
        const int g = i >> 10, n = i & 1023;
        g_bias0[i] = (g == 0) ? bi[n] : (g == 1) ? bf[n] : (g == 2) ? bo[n] : bg[n];
    }
    if (i < 1024) g_bias1[i] = bh[i] + bc[i];
}

// ---------------------------------------------------------------------------
// tf32 MMA GEMM. CTA tile 128(M) x 256(N) x 32(K), 256 threads = 8 warps in
// 2(M) x 4(N); warp tile 64x64 (4 m16-tiles x 8 n8-tiles) -> 4 B LDS per MMA
// per lane (LDS:MMA = 1:1). 3-stage cp.async pipeline; swizzled row-major
// smem [row][k0..31], chunk ^= row&7. Fragment k-slot permutation: hw slot t
// holds data k=2t, slot t+4 holds k=2t+1, identically for A and B.
// MODE 0: out fp32 = acc + bias               (preact)
// MODE 1: out tf32 = cvt(acc + bias + addend) (resid)
// MODE 2: out fp32 = acc + bias               (prediction)
// ---------------------------------------------------------------------------
template<int MODE, int KD>
__global__ __launch_bounds__(256)
void mma_gemm(const float* __restrict__ A, const float* __restrict__ W,
              const float* __restrict__ bias, const float* __restrict__ addend,
              float* __restrict__ out, int ldo)
{
    extern __shared__ float smf[];
    const int tid  = threadIdx.x;
    const int w    = tid >> 5, lane = tid & 31;
    const int wm   = w >> 2,  wn = w & 3;         // 2 x 4 warp grid
    const int grp  = lane >> 2, tig = lane & 3;
    const int tigHi = tig >> 1, tigLo2 = (tig & 1) << 1;
    const int m0 = blockIdx.y * 128;
    const int n0 = blockIdx.x * 256;
    constexpr int STAGEF = 12288;                 // 48KB per stage (A 16K + B 32K)
    constexpr int nK = KD / 32;

    float acc[4][8][4];
#pragma unroll
    for (int i = 0; i < 4; i++)
#pragma unroll
        for (int j = 0; j < 8; j++)
#pragma unroll
            for (int v = 0; v < 4; v++) acc[i][j][v] = 0.0f;

    auto stage = [&](int kt) {
        const uint32_t base = smem_u32(smf + (kt % 3) * STAGEF);
#pragma unroll
        for (int j = 0; j < 4; j++) {             // A: 128 rows x 8 chunks
            const int i = tid + j * 256;
            const int row = i >> 3, c = i & 7;
            cp16(base + row * 128 + ((c ^ (row & 7)) << 4),
                 A + (size_t)(m0 + row) * KD + kt * 32 + c * 4);
        }
#pragma unroll
        for (int j = 0; j < 8; j++) {             // B: 256 rows x 8 chunks
            const int i = tid + j * 256;
            const int row = i >> 3, c = i & 7;
            cp16(base + 16384 + row * 128 + ((c ^ (row & 7)) << 4),
                 W + (size_t)(n0 + row) * KD + kt * 32 + c * 4);
        }
        asm volatile("cp.async.commit_group;" ::: "memory");
    };

    stage(0);
    stage(1);

    for (int kt = 0; kt < nK; kt++) {
        asm volatile("cp.async.wait_group 1;" ::: "memory");
        __syncthreads();
        const float* As = smf + (kt % 3) * STAGEF;
        const float* Bs = As + 4096;

#pragma unroll
        for (int k8 = 0; k8 < 4; k8++) {
            // swizzle XOR collapses: every fragment row has (row & 7) == grp
            const int coff = (((k8 * 2 + tigHi) ^ grp) << 2) + tigLo2;

            uint32_t af[4][4];
#pragma unroll
            for (int mi = 0; mi < 4; mi++) {
                const int r = wm * 64 + mi * 16 + grp;
                const float2 x = *reinterpret_cast<const float2*>(As + r * 32 + coff);
                const float2 y = *reinterpret_cast<const float2*>(As + (r + 8) * 32 + coff);
                af[mi][0] = __float_as_uint(x.x); af[mi][1] = __float_as_uint(y.x);
                af[mi][2] = __float_as_uint(x.y); af[mi][3] = __float_as_uint(y.y);
            }
#pragma unroll
            for (int nj = 0; nj < 8; nj++) {
                const int r = wn * 64 + nj * 8 + grp;
                const float2 x = *reinterpret_cast<const float2*>(Bs + r * 32 + coff);
                uint32_t bb[2] = { __float_as_uint(x.x), __float_as_uint(x.y) };
#pragma unroll
                for (int mi = 0; mi < 4; mi++) mma_tf32(acc[mi][nj], af[mi], bb);
            }
        }
        if (kt + 2 < nK) stage(kt + 2);
    }

    // ---- epilogue: STG.64 segments ----
    const int gc = tig * 2;
#pragma unroll
    for (int mi = 0; mi < 4; mi++) {
        const int gm = m0 + wm * 64 + mi * 16 + grp;
#pragma unroll
        for (int nj = 0; nj < 8; nj++) {
            const int gn = n0 + wn * 64 + nj * 8 + gc;
            const float bv0 = bias[gn], bv1 = bias[gn + 1];
            float2 r0 = make_float2(acc[mi][nj][0] + bv0, acc[mi][nj][1] + bv1);
            float2 r1 = make_float2(acc[mi][nj][2] + bv0, acc[mi][nj][3] + bv1);
            if (MODE == 1) {
                const float2 d0 = *reinterpret_cast<const float2*>(
                    addend + (size_t)gm * 1024 + gn);
                const float2 d1 = *reinterpret_cast<const float2*>(
                    addend + (size_t)(gm + 8) * 1024 + gn);
                r0 = make_float2(f2tf(r0.x + d0.x), f2tf(r0.y + d0.y));
                r1 = make_float2(f2tf(r1.x + d1.x), f2tf(r1.y + d1.y));
            }
            *reinterpret_cast<float2*>(out + (size_t)gm * ldo + gn)       = r0;
            *reinterpret_cast<float2*>(out + (size_t)(gm + 8) * ldo + gn) = r1;
        }
    }
}

// ---------------------------------------------------------------------------
// Elementwise LSTM cell; emits fp32 hidden/cell to output and tf32 hidden
// into A1cat[:, 0:1024].
// ---------------------------------------------------------------------------
__device__ __forceinline__ float sigf(float x) { return 1.0f / (1.0f + __expf(-x)); }
__device__ __forceinline__ float tanhfast(float x) { return 2.0f * sigf(2.0f * x) - 1.0f; }

__global__ void lstm_elem(const float4* __restrict__ pre,
                          const float4* __restrict__ cprev,
                          float4* __restrict__ hidden,
                          float4* __restrict__ cell)
{
    const int idx = blockIdx.x * blockDim.x + threadIdx.x;
    const int b  = idx >> 8;
    const int h4 = idx & 255;
    const size_t base = (size_t)b * 1024;
    const float4 pi = pre[base + h4];
    const float4 pf = pre[base + 256 + h4];
    const float4 po = pre[base + 512 + h4];
    const float4 pg = pre[base + 768 + h4];
    const float4 cp = cprev[idx];

    const float c0 = sigf(pf.x) * cp.x + sigf(pi.x) * tanhfast(pg.x);
    const float c1 = sigf(pf.y) * cp.y + sigf(pi.y) * tanhfast(pg.y);
    const float c2 = sigf(pf.z) * cp.z + sigf(pi.z) * tanhfast(pg.z);
    const float c3 = sigf(pf.w) * cp.w + sigf(pi.w) * tanhfast(pg.w);

    const float h0 = sigf(po.x) * tanhfast(c0);
    const float h1 = sigf(po.y) * tanhfast(c1);
    const float h2 = sigf(po.z) * tanhfast(c2);
    const float h3 = sigf(po.w) * tanhfast(c3);

    cell[idx]   = make_float4(c0, c1, c2, c3);
    hidden[idx] = make_float4(h0, h1, h2, h3);

    float4* a1 = reinterpret_cast<float4*>(g_A1cat + (size_t)b * 2048 + h4 * 4);
    *a1 = make_float4(f2tf(h0), f2tf(h1), f2tf(h2), f2tf(h3));
}

// ---------------------------------------------------------------------------
extern "C" void kernel_launch(void* const* d_in, const int* in_sizes, int n_in,
                              void* d_out, int out_size)
{
    (void)in_sizes; (void)n_in; (void)out_size;

    const float* emb = (const float*)d_in[0];
    const float* hid = (const float*)d_in[1];
    const float* cpr = (const float*)d_in[2];
    const float* ctx = (const float*)d_in[3];
    const float* Wi  = (const float*)d_in[4];  const float* bi = (const float*)d_in[5];
    const float* Wf  = (const float*)d_in[6];  const float* bf = (const float*)d_in[7];
    const float* Wo  = (const float*)d_in[8];  const float* bo = (const float*)d_in[9];
    const float* Wg  = (const float*)d_in[10]; const float* bg = (const float*)d_in[11];
    const float* Wc  = (const float*)d_in[12]; const float* bc = (const float*)d_in[13];
    const float* Wh  = (const float*)d_in[14]; const float* bh = (const float*)d_in[15];
    const float* Wp  = (const float*)d_in[16]; const float* bp = (const float*)d_in[17];

    float* out     = (float*)d_out;
    float* pred    = out;
    float* hiddenO = out + (size_t)BB * EE;
    float* cellO   = hiddenO + (size_t)BB * HH;

    float *preP, *AcatP, *WgP, *A1P, *WhcP, *WpP, *residP, *b0P, *b1P;
    cudaGetSymbolAddress((void**)&preP,   g_preact);
    cudaGetSymbolAddress((void**)&AcatP,  g_Acat);
    cudaGetSymbolAddress((void**)&WgP,    g_Wgcat);
    cudaGetSymbolAddress((void**)&A1P,    g_A1cat);
    cudaGetSymbolAddress((void**)&WhcP,   g_Whc);
    cudaGetSymbolAddress((void**)&WpP,    g_Wpt);
    cudaGetSymbolAddress((void**)&residP, g_residT);
    cudaGetSymbolAddress((void**)&b0P,    g_bias0);
    cudaGetSymbolAddress((void**)&b1P,    g_bias1);

    const int T = 256;
    // ---- precompute: tf32 conversions + concats (proven in R5) ----
    {
        const int n4 = BB * 256;
        cvt_seg<<<(n4 + T - 1) / T, T>>>(emb, AcatP, 256, DD, 0,    n4);
        cvt_seg<<<(n4 + T - 1) / T, T>>>(hid, AcatP, 256, DD, 1024, n4);
        cvt_seg<<<(n4 + T - 1) / T, T>>>(ctx, AcatP, 256, DD, 2048, n4);
        cvt_seg<<<(n4 + T - 1) / T, T>>>(ctx, A1P, 256, 2048, 1024, n4);
    }
    {
        const int n4 = HH * (DD / 4);
        cvt_seg<<<(n4 + T - 1) / T, T>>>(Wi, WgP,                       DD / 4, DD, 0, n4);
        cvt_seg<<<(n4 + T - 1) / T, T>>>(Wf, WgP + (size_t)1 * HH * DD, DD / 4, DD, 0, n4);
        cvt_seg<<<(n4 + T - 1) / T, T>>>(Wo, WgP + (size_t)2 * HH * DD, DD / 4, DD, 0, n4);
        cvt_seg<<<(n4 + T - 1) / T, T>>>(Wg, WgP + (size_t)3 * HH * DD, DD / 4, DD, 0, n4);
    }
    {
        const int n4 = EE * 256;
        cvt_seg<<<(n4 + T - 1) / T, T>>>(Wh, WhcP, 256, 2048, 0,    n4);
        cvt_seg<<<(n4 + T - 1) / T, T>>>(Wc, WhcP, 256, 2048, 1024, n4);
        cvt_seg<<<(n4 + T - 1) / T, T>>>(Wp, WpP,  256, 1024, 0,    n4);
    }
    bias_prep<<<16, 256>>>(bi, bf, bo, bg, bh, bc);

    const int SMEM = 3 * 12288 * sizeof(float);  // 147456
    cudaFuncSetAttribute(mma_gemm<0, DD>,   cudaFuncAttributeMaxDynamicSharedMemorySize, SMEM);
    cudaFuncSetAttribute(mma_gemm<1, 2048>, cudaFuncAttributeMaxDynamicSharedMemorySize, SMEM);
    cudaFuncSetAttribute(mma_gemm<2, 1024>, cudaFuncAttributeMaxDynamicSharedMemorySize, SMEM);

    // ---- 1) gates: [B,4H] preact ----
    mma_gemm<0, DD><<<dim3(16, 32), 256, SMEM>>>(AcatP, WgP, b0P, nullptr, preP, 4 * HH);

    // ---- 2) cell update (also writes tf32 hidden into A1cat) ----
    lstm_elem<<<4096, 256>>>((const float4*)preP, (const float4*)cpr,
                             (float4*)hiddenO, (float4*)cellO);

    // ---- 3) resid (tf32) = cvt(emb + hidden@Wh^T + ctx@Wc^T + bh+bc) ----
    mma_gemm<1, 2048><<<dim3(4, 32), 256, SMEM>>>(A1P, WhcP, b1P, emb, residP, EE);

    // ---- 4) prediction = resid @ Wp^T + bp ----
    mma_gemm<2, 1024><<<dim3(4, 32), 256, SMEM>>>(residP, WpP, bp, nullptr, pred, EE);
}

// round 11
// speedup vs baseline: 4.3605x; 2.4172x over previous
#include <cuda_runtime.h>
#include <cuda_fp16.h>
#include <cstdint>
#include <math.h>

#define BB 4096
#define EE 1024
#define HH 1024
#define CC 1024
#define DD 3072

// ---- scratch (device globals; allocation-rule-safe) ----
__device__ float g_preact[(size_t)BB * 4 * HH];            // [B,4H] fp32 preacts
__device__ float g_bias0 [4 * HH];
__device__ float g_bias1 [EE];
__device__ __align__(16) __half g_embH  [(size_t)BB * EE];
__device__ __align__(16) __half g_hidIH [(size_t)BB * HH];   // input prev hidden
__device__ __align__(16) __half g_ctxH  [(size_t)BB * CC];
__device__ __align__(16) __half g_WgH   [(size_t)4 * HH * DD];
__device__ __align__(16) __half g_WhH   [(size_t)EE * HH];
__device__ __align__(16) __half g_WcH   [(size_t)EE * CC];
__device__ __align__(16) __half g_WpH   [(size_t)EE * EE];
__device__ __align__(16) __half g_hidcH [(size_t)BB * HH];   // computed hidden
__device__ __align__(16) __half g_residH[(size_t)BB * EE];

__device__ __forceinline__ uint32_t smem_u32(const void* p) {
    uint32_t a;
    asm("{ .reg .u64 t; cvta.to.shared.u64 t, %1; cvt.u32.u64 %0, t; }" : "=r"(a) : "l"(p));
    return a;
}
__device__ __forceinline__ void cp16h(uint32_t d, const __half* g) {
    asm volatile("cp.async.cg.shared.global [%0], [%1], 16;" :: "r"(d), "l"((const void*)g));
}
__device__ __forceinline__ void mma_f16(float* c, const uint32_t* a, uint32_t b0, uint32_t b1) {
    asm volatile(
        "mma.sync.aligned.m16n8k16.row.col.f32.f16.f16.f32 "
        "{%0,%1,%2,%3}, {%4,%5,%6,%7}, {%8,%9}, {%0,%1,%2,%3};"
        : "+f"(c[0]), "+f"(c[1]), "+f"(c[2]), "+f"(c[3])
        : "r"(a[0]), "r"(a[1]), "r"(a[2]), "r"(a[3]), "r"(b0), "r"(b1));
}
#define LDSM4(r, addr) \
    asm volatile("ldmatrix.sync.aligned.m8n8.x4.shared.b16 {%0,%1,%2,%3}, [%4];" \
        : "=r"((r)[0]), "=r"((r)[1]), "=r"((r)[2]), "=r"((r)[3]) : "r"(addr))

// ---------------------------------------------------------------------------
// Flat fp32 -> fp16 conversion (contiguous). 8 elements per thread.
// ---------------------------------------------------------------------------
__global__ void cvt_h(const float4* __restrict__ src, uint4* __restrict__ dst, int total8)
{
    const int i = blockIdx.x * blockDim.x + threadIdx.x;
    if (i >= total8) return;
    const float4 v0 = src[2 * i], v1 = src[2 * i + 1];
    union { uint4 u; __half2 h[4]; } o;
    o.h[0] = __float22half2_rn(make_float2(v0.x, v0.y));
    o.h[1] = __float22half2_rn(make_float2(v0.z, v0.w));
    o.h[2] = __float22half2_rn(make_float2(v1.x, v1.y));
    o.h[3] = __float22half2_rn(make_float2(v1.z, v1.w));
    dst[i] = o.u;
}

__global__ void bias_prep(const float* __restrict__ bi, const float* __restrict__ bf,
                          const float* __restrict__ bo, const float* __restrict__ bg,
                          const float* __restrict__ bh, const float* __restrict__ bc)
{
    const int i = blockIdx.x * blockDim.x + threadIdx.x;
    if (i < 4096) {
        const int g = i >> 10, n = i & 1023;
        g_bias0[i] = (g == 0) ? bi[n] : (g == 1) ? bf[n] : (g == 2) ? bo[n] : bg[n];
    }
    if (i < 1024) g_bias1[i] = bh[i] + bc[i];
}

// ---------------------------------------------------------------------------
// fp16 MMA GEMM.  CTA tile 128x128x32, 128 threads = 4 warps (2Mx2N), warp
// tile 64x64 (4 m16 x 8 n8, k16 MMA).  3-stage cp.async, ldmatrix.x4 frags.
// smem row = 32 halves = 64B, 4 chunks of 16B, swizzle chunk ^= (row>>1)&3.
// MODE 0: gates  A=seg(emb,hidI,ctx)   B=Wg[gate]  out fp32 preact (ldo 4096)
// MODE 1: resid  A=seg(hidc,ctx)       B=seg(Wh,Wc) out fp16 resid (+bias+emb)
// MODE 2: pred   A=resid               B=Wp         out fp32 pred
// ---------------------------------------------------------------------------
template<int MODE, int KD>
__global__ __launch_bounds__(128, 2)
void hgemm(const __half* __restrict__ A0, const __half* __restrict__ A1,
           const __half* __restrict__ A2,
           const __half* __restrict__ W0, const __half* __restrict__ W1,
           const float* __restrict__ bias, const float* __restrict__ addend,
           float* __restrict__ outF, __half* __restrict__ outH, int ldo)
{
    extern __shared__ __align__(1024) char smc[];
    const uint32_t sb = smem_u32(smc);
    const int tid = threadIdx.x;
    const int w = tid >> 5, lane = tid & 31;
    const int wm = w >> 1, wn = w & 1;
    const int grp = lane >> 2, tig = lane & 3;
    const int m0 = blockIdx.y * 128;
    const int n0 = blockIdx.x * 128;
    constexpr int nK = KD / 32;

    // MODE0 gate select (CTA N=128 within one gate)
    const __half* Wsel = W0;
    if (MODE == 0) Wsel = W0 + (size_t)(n0 >> 10) * 1024 * DD;
    const int nloc0 = n0 & 1023;

    float acc[4][8][4];
#pragma unroll
    for (int i = 0; i < 4; i++)
#pragma unroll
        for (int j = 0; j < 8; j++)
#pragma unroll
            for (int v = 0; v < 4; v++) acc[i][j][v] = 0.0f;

    // ---- per-lane ldmatrix relative addresses (stage-base-free) ----
    // A x4: mat = lane>>3; rows m..+7 / m+8..+15 x khalf 0/1
    uint32_t relA, relB;
    {
        const int mat = lane >> 3;
        const int ar  = wm * 64 + (lane & 7) + (mat & 1) * 8;   // + mi*16
        const int akh = mat >> 1;
        const uint32_t sw = (ar >> 1) & 3;
        relA = ar * 64 + (((((sw >> 1)) << 1) | (akh ^ (sw & 1))) << 4);
        const int br  = wn * 64 + (lane & 7) + (mat >> 1) * 8;  // + njp*16
        const int bkh = mat & 1;
        const uint32_t swb = (br >> 1) & 3;
        relB = 8192 + br * 64 + (((((swb >> 1)) << 1) | (bkh ^ (swb & 1))) << 4);
    }

    auto stage = [&](int kt) {
        const uint32_t base = sb + (kt % 3) * 16384;
        const int kb = kt * 32;
#pragma unroll
        for (int j = 0; j < 4; j++) {                 // A: 128 rows x 4 chunks
            const int i = tid + j * 128;
            const int row = i >> 2, c = i & 3;
            const uint32_t d = base + row * 64 + ((c ^ ((row >> 1) & 3)) << 4);
            const __half* gp;
            if (MODE == 0) {
                const int seg = kb >> 10;
                const __half* s0 = (seg == 0) ? A0 : (seg == 1) ? A1 : A2;
                gp = s0 + (size_t)(m0 + row) * 1024 + (kb & 1023) + c * 8;
            } else if (MODE == 1) {
                const __half* s0 = (kb >> 10) ? A1 : A0;
                gp = s0 + (size_t)(m0 + row) * 1024 + (kb & 1023) + c * 8;
            } else {
                gp = A0 + (size_t)(m0 + row) * 1024 + kb + c * 8;
            }
            cp16h(d, gp);
        }
#pragma unroll
        for (int j = 0; j < 4; j++) {                 // B: 128 rows x 4 chunks
            const int i = tid + j * 128;
            const int row = i >> 2, c = i & 3;
            const uint32_t d = base + 8192 + row * 64 + ((c ^ ((row >> 1) & 3)) << 4);
            const __half* gp;
            if (MODE == 0) {
                gp = Wsel + (size_t)(nloc0 + row) * DD + kb + c * 8;
            } else if (MODE == 1) {
                const __half* s0 = (kb >> 10) ? W1 : W0;
                gp = s0 + (size_t)(n0 + row) * 1024 + (kb & 1023) + c * 8;
            } else {
                gp = W0 + (size_t)(n0 + row) * 1024 + kb + c * 8;
            }
            cp16h(d, gp);
        }
        asm volatile("cp.async.commit_group;" ::: "memory");
    };

    stage(0);
    stage(1);

    for (int kt = 0; kt < nK; kt++) {
        asm volatile("cp.async.wait_group 1;" ::: "memory");
        __syncthreads();
        const uint32_t stg = sb + (kt % 3) * 16384;
        if (kt + 2 < nK) stage(kt + 2);

#pragma unroll
        for (int s = 0; s < 2; s++) {
            const uint32_t sx = s << 5;
            uint32_t a[4][4];
#pragma unroll
            for (int mi = 0; mi < 4; mi++)
                LDSM4(a[mi], stg + ((relA + mi * 1024) ^ sx));
            uint32_t b[4][4];
#pragma unroll
            for (int njp = 0; njp < 4; njp++)
                LDSM4(b[njp], stg + ((relB + njp * 1024) ^ sx));
#pragma unroll
            for (int njp = 0; njp < 4; njp++)
#pragma unroll
                for (int mi = 0; mi < 4; mi++) {
                    mma_f16(acc[mi][2 * njp],     a[mi], b[njp][0], b[njp][1]);
                    mma_f16(acc[mi][2 * njp + 1], a[mi], b[njp][2], b[njp][3]);
                }
        }
        __syncthreads();
    }

    // ---- epilogue ----
    const int gc = tig * 2;
#pragma unroll
    for (int mi = 0; mi < 4; mi++) {
        const int gm = m0 + wm * 64 + mi * 16 + grp;
#pragma unroll
        for (int nj = 0; nj < 8; nj++) {
            const int gn = n0 + wn * 64 + nj * 8 + gc;
            const float bv0 = bias[gn], bv1 = bias[gn + 1];
            float2 r0 = make_float2(acc[mi][nj][0] + bv0, acc[mi][nj][1] + bv1);
            float2 r1 = make_float2(acc[mi][nj][2] + bv0, acc[mi][nj][3] + bv1);
            if (MODE == 1) {
                const float2 d0 = *reinterpret_cast<const float2*>(
                    addend + (size_t)gm * 1024 + gn);
                const float2 d1 = *reinterpret_cast<const float2*>(
                    addend + (size_t)(gm + 8) * 1024 + gn);
                r0.x += d0.x; r0.y += d0.y; r1.x += d1.x; r1.y += d1.y;
                *reinterpret_cast<__half2*>(outH + (size_t)gm * 1024 + gn) =
                    __float22half2_rn(r0);
                *reinterpret_cast<__half2*>(outH + (size_t)(gm + 8) * 1024 + gn) =
                    __float22half2_rn(r1);
            } else {
                *reinterpret_cast<float2*>(outF + (size_t)gm * ldo + gn)       = r0;
                *reinterpret_cast<float2*>(outF + (size_t)(gm + 8) * ldo + gn) = r1;
            }
        }
    }
}

// ---------------------------------------------------------------------------
// Elementwise LSTM cell; fp32 hidden/cell to output, fp16 hidden to g_hidcH.
// ---------------------------------------------------------------------------
__device__ __forceinline__ float sigf(float x) { return 1.0f / (1.0f + __expf(-x)); }
__device__ __forceinline__ float tanhfast(float x) { return 2.0f * sigf(2.0f * x) - 1.0f; }

__global__ void lstm_elem(const float4* __restrict__ pre,
                          const float4* __restrict__ cprev,
                          float4* __restrict__ hidden,
                          float4* __restrict__ cell)
{
    const int idx = blockIdx.x * blockDim.x + threadIdx.x;
    const int b  = idx >> 8;
    const int h4 = idx & 255;
    const size_t base = (size_t)b * 1024;
    const float4 pi = pre[base + h4];
    const float4 pf = pre[base + 256 + h4];
    const float4 po = pre[base + 512 + h4];
    const float4 pg = pre[base + 768 + h4];
    const float4 cp = cprev[idx];

    const float c0 = sigf(pf.x) * cp.x + sigf(pi.x) * tanhfast(pg.x);
    const float c1 = sigf(pf.y) * cp.y + sigf(pi.y) * tanhfast(pg.y);
    const float c2 = sigf(pf.z) * cp.z + sigf(pi.z) * tanhfast(pg.z);
    const float c3 = sigf(pf.w) * cp.w + sigf(pi.w) * tanhfast(pg.w);

    const float h0 = sigf(po.x) * tanhfast(c0);
    const float h1 = sigf(po.y) * tanhfast(c1);
    const float h2 = sigf(po.z) * tanhfast(c2);
    const float h3 = sigf(po.w) * tanhfast(c3);

    cell[idx]   = make_float4(c0, c1, c2, c3);
    hidden[idx] = make_float4(h0, h1, h2, h3);

    __half2* hh = reinterpret_cast<__half2*>(g_hidcH);
    hh[idx * 2]     = __float22half2_rn(make_float2(h0, h1));
    hh[idx * 2 + 1] = __float22half2_rn(make_float2(h2, h3));
}

// ---------------------------------------------------------------------------
extern "C" void kernel_launch(void* const* d_in, const int* in_sizes, int n_in,
                              void* d_out, int out_size)
{
    (void)in_sizes; (void)n_in; (void)out_size;

    const float* emb = (const float*)d_in[0];
    const float* hid = (const float*)d_in[1];
    const float* cpr = (const float*)d_in[2];
    const float* ctx = (const float*)d_in[3];
    const float* Wi  = (const float*)d_in[4];  const float* bi = (const float*)d_in[5];
    const float* Wf  = (const float*)d_in[6];  const float* bf = (const float*)d_in[7];
    const float* Wo  = (const float*)d_in[8];  const float* bo = (const float*)d_in[9];
    const float* Wg  = (const float*)d_in[10]; const float* bg = (const float*)d_in[11];
    const float* Wc  = (const float*)d_in[12]; const float* bc = (const float*)d_in[13];
    const float* Wh  = (const float*)d_in[14]; const float* bh = (const float*)d_in[15];
    const float* Wp  = (const float*)d_in[16]; const float* bp = (const float*)d_in[17];

    float* out     = (float*)d_out;
    float* pred    = out;
    float* hiddenO = out + (size_t)BB * EE;
    float* cellO   = hiddenO + (size_t)BB * HH;

    float *preP, *b0P, *b1P;
    __half *embH, *hidIH, *ctxH, *WgHp, *WhHp, *WcHp, *WpHp, *hidcH, *residH;
    cudaGetSymbolAddress((void**)&preP,   g_preact);
    cudaGetSymbolAddress((void**)&b0P,    g_bias0);
    cudaGetSymbolAddress((void**)&b1P,    g_bias1);
    cudaGetSymbolAddress((void**)&embH,   g_embH);
    cudaGetSymbolAddress((void**)&hidIH,  g_hidIH);
    cudaGetSymbolAddress((void**)&ctxH,   g_ctxH);
    cudaGetSymbolAddress((void**)&WgHp,   g_WgH);
    cudaGetSymbolAddress((void**)&WhHp,   g_WhH);
    cudaGetSymbolAddress((void**)&WcHp,   g_WcH);
    cudaGetSymbolAddress((void**)&WpHp,   g_WpH);
    cudaGetSymbolAddress((void**)&hidcH,  g_hidcH);
    cudaGetSymbolAddress((void**)&residH, g_residH);

    // ---- flat fp16 conversions ----
    const int T = 256;
    const int nBE = BB * EE / 8;          // 524288
    const int nW  = HH * DD / 8;          // 393216
    const int nWs = EE * EE / 8;          // 131072
    cvt_h<<<nBE / T, T>>>((const float4*)emb, (uint4*)embH,  nBE);
    cvt_h<<<nBE / T, T>>>((const float4*)hid, (uint4*)hidIH, nBE);
    cvt_h<<<nBE / T, T>>>((const float4*)ctx, (uint4*)ctxH,  nBE);
    cvt_h<<<nW  / T, T>>>((const float4*)Wi,  (uint4*)(WgHp),                          nW);
    cvt_h<<<nW  / T, T>>>((const float4*)Wf,  (uint4*)(WgHp + (size_t)1 * HH * DD),    nW);
    cvt_h<<<nW  / T, T>>>((const float4*)Wo,  (uint4*)(WgHp + (size_t)2 * HH * DD),    nW);
    cvt_h<<<nW  / T, T>>>((const float4*)Wg,  (uint4*)(WgHp + (size_t)3 * HH * DD),    nW);
    cvt_h<<<nWs / T, T>>>((const float4*)Wh,  (uint4*)WhHp, nWs);
    cvt_h<<<nWs / T, T>>>((const float4*)Wc,  (uint4*)WcHp, nWs);
    cvt_h<<<nWs / T, T>>>((const float4*)Wp,  (uint4*)WpHp, nWs);
    bias_prep<<<16, 256>>>(bi, bf, bo, bg, bh, bc);

    const int SMEM = 3 * 16384;   // 48KB -> 2 CTAs/SM
    cudaFuncSetAttribute(hgemm<0, DD>,   cudaFuncAttributeMaxDynamicSharedMemorySize, SMEM);
    cudaFuncSetAttribute(hgemm<1, 2048>, cudaFuncAttributeMaxDynamicSharedMemorySize, SMEM);
    cudaFuncSetAttribute(hgemm<2, 1024>, cudaFuncAttributeMaxDynamicSharedMemorySize, SMEM);

    // 1) gates preact [B,4H]
    hgemm<0, DD><<<dim3(32, 32), 128, SMEM>>>(
        embH, hidIH, ctxH, WgHp, nullptr, b0P, nullptr, preP, nullptr, 4 * HH);

    // 2) cell update
    lstm_elem<<<4096, 256>>>((const float4*)preP, (const float4*)cpr,
                             (float4*)hiddenO, (float4*)cellO);

    // 3) resid (fp16) = emb + hidden@Wh^T + ctx@Wc^T + bh+bc
    hgemm<1, 2048><<<dim3(8, 32), 128, SMEM>>>(
        hidcH, ctxH, nullptr, WhHp, WcHp, b1P, emb, nullptr, residH, EE);

    // 4) prediction = resid @ Wp^T + bp
    hgemm<2, 1024><<<dim3(8, 32), 128, SMEM>>>(
        residH, nullptr, nullptr, WpHp, nullptr, bp, nullptr, pred, nullptr, EE);
}